// round 1
// baseline (speedup 1.0000x reference)
#include <cuda_runtime.h>

// Problem constants
#define BB 2
#define SS 2048
#define HH 16
#define DK 64
#define DM 1024
#define ROWS (BB*SS)          // 4096

// ---------------- scratch (static device globals; no runtime allocation) ----
__device__ float g_Qh[(size_t)BB*HH*SS*DK];     // [b,h,s,d] 16 MB
__device__ float g_Kh[(size_t)BB*HH*SS*DK];     // 16 MB
__device__ float g_Vp[(size_t)ROWS*DK];         // 1 MB
__device__ float g_scores[(size_t)BB*HH*SS*SS]; // 536 MB raw scaled scores
__device__ float g_m[(size_t)BB*HH*SS];
__device__ float g_l[(size_t)BB*HH*SS];
__device__ float g_ao[(size_t)ROWS*DK];         // attn_output [4096,64]

// ---------------- generic tiled SGEMM ---------------------------------------
// C[M,N] = scale * A[M,K] @ (TRANS_B ? B[N,K]^T : B[K,N]) (+ bias[col])
// 128x128 tile, 256 threads, 8x8 microtile, k-chunk 16.
// M must be a multiple of 128, K a multiple of 16. N may be < tile (guarded).
#define TS 128
#define KC 16
#define PADW 132   // padded smem row stride (floats), 16B-aligned

template<bool TRANS_B, bool HEAD_OUT, bool HAS_BIAS>
__global__ __launch_bounds__(256)
void sgemm_kernel(const float* __restrict__ A, const float* __restrict__ B,
                  const float* __restrict__ bias, float* __restrict__ C,
                  int M, int N, int K, int lda, int ldb, int ldc,
                  long long strideA, long long strideB, long long strideC,
                  float scale)
{
    __shared__ __align__(16) float As[KC * PADW];
    __shared__ __align__(16) float Bs[KC * PADW];

    int z = blockIdx.z;
    A += (long long)z * strideA;
    B += (long long)z * strideB;
    C += (long long)z * strideC;

    const int rowbase = blockIdx.y * TS;
    const int colbase = blockIdx.x * TS;
    const int tid = threadIdx.x;
    const int tx = tid & 15, ty = tid >> 4;
    const int row0 = ty * 8, col0 = tx * 8;

    float acc[8][8];
#pragma unroll
    for (int i = 0; i < 8; i++)
#pragma unroll
        for (int j = 0; j < 8; j++) acc[i][j] = 0.f;

    for (int k0 = 0; k0 < K; k0 += KC) {
        // A tile: As[kk][r] = A[rowbase+r, k0+kk]
#pragma unroll
        for (int i = 0; i < 8; i++) {
            int idx = tid + i * 256;      // 0..2047
            int r = idx >> 4, kk = idx & 15;
            As[kk * PADW + r] = A[(long long)(rowbase + r) * lda + k0 + kk];
        }
        // B tile: Bs[kk][c]
        if (TRANS_B) {
#pragma unroll
            for (int i = 0; i < 8; i++) {
                int idx = tid + i * 256;
                int c = idx >> 4, kk = idx & 15;
                int col = colbase + c;
                float v = 0.f;
                if (col < N) v = B[(long long)col * ldb + k0 + kk];
                Bs[kk * PADW + c] = v;
            }
        } else {
#pragma unroll
            for (int i = 0; i < 8; i++) {
                int idx = tid + i * 256;
                int kk = idx >> 7, c = idx & 127;
                int col = colbase + c;
                float v = 0.f;
                if (col < N) v = B[(long long)(k0 + kk) * ldb + col];
                Bs[kk * PADW + c] = v;
            }
        }
        __syncthreads();

#pragma unroll
        for (int kk = 0; kk < KC; kk++) {
            float4 a0 = *(const float4*)&As[kk * PADW + row0];
            float4 a1 = *(const float4*)&As[kk * PADW + row0 + 4];
            float4 b0 = *(const float4*)&Bs[kk * PADW + col0];
            float4 b1 = *(const float4*)&Bs[kk * PADW + col0 + 4];
            float a[8] = {a0.x, a0.y, a0.z, a0.w, a1.x, a1.y, a1.z, a1.w};
            float b[8] = {b0.x, b0.y, b0.z, b0.w, b1.x, b1.y, b1.z, b1.w};
#pragma unroll
            for (int i = 0; i < 8; i++)
#pragma unroll
                for (int j = 0; j < 8; j++)
                    acc[i][j] += a[i] * b[j];
        }
        __syncthreads();
    }

    // epilogue
#pragma unroll
    for (int i = 0; i < 8; i++) {
        int gr = rowbase + row0 + i;
#pragma unroll
        for (int j = 0; j < 8; j++) {
            int col = colbase + col0 + j;
            if (col < N) {
                float v = acc[i][j] * scale;
                if (HAS_BIAS) v += bias[col];
                if (HEAD_OUT) {
                    // [b,s] row -> [b,h,s,d] interleaved output
                    int b = gr >> 11, s = gr & (SS - 1);
                    int h = col >> 6, d = col & (DK - 1);
                    C[((long long)((b * HH + h) * SS + s) << 6) + d] = v;
                } else {
                    C[(long long)gr * ldc + col] = v;
                }
            }
        }
    }
}

// ---------------- per-row softmax stats (one warp per score row) ------------
__global__ __launch_bounds__(256)
void rowstats_kernel(const float* __restrict__ scores,
                     float* __restrict__ mbuf, float* __restrict__ lbuf)
{
    int row = blockIdx.x * 8 + (threadIdx.x >> 5); // [0, B*H*S)
    int lane = threadIdx.x & 31;
    const float* p = scores + (long long)row * SS;

    float m = -1e30f, l = 0.f;
    for (int k = lane; k < SS; k += 32) {
        float x = p[k];
        if (x > m) { l *= __expf(m - x); m = x; }
        l += __expf(x - m);
    }
    // combine across lanes
#pragma unroll
    for (int o = 16; o; o >>= 1) {
        float mo = __shfl_xor_sync(0xffffffffu, m, o);
        float lo = __shfl_xor_sync(0xffffffffu, l, o);
        float mn = fmaxf(m, mo);
        l = l * __expf(m - mn) + lo * __expf(mo - mn);
        m = mn;
    }
    if (lane == 0) { mbuf[row] = m; lbuf[row] = l; }
}

// ---------------- head-averaged attention matrix ----------------------------
// avg[b,q,k] = (1/H) * sum_h exp(scores[b,h,q,k] - m[b,h,q]) / l[b,h,q]
__global__ __launch_bounds__(256)
void avg_kernel(const float* __restrict__ scores,
                const float* __restrict__ mbuf, const float* __restrict__ lbuf,
                float* __restrict__ avg)
{
    int q = blockIdx.x;
    int b = blockIdx.y;
    int tid = threadIdx.x;

    __shared__ float sm[HH], sz[HH];
    if (tid < HH) {
        int row = (b * HH + tid) * SS + q;
        sm[tid] = mbuf[row];
        sz[tid] = 1.0f / lbuf[row];
    }
    __syncthreads();

    const long long base = ((long long)b * HH * SS + q) * SS;
    for (int k = tid; k < SS; k += 256) {
        float a = 0.f;
#pragma unroll
        for (int h = 0; h < HH; h++) {
            float s = scores[base + (long long)h * SS * SS + k];
            a += __expf(s - sm[h]) * sz[h];
        }
        avg[((long long)b * SS + q) * SS + k] = a * (1.0f / HH);
    }
}

// ---------------- launch -----------------------------------------------------
extern "C" void kernel_launch(void* const* d_in, const int* in_sizes, int n_in,
                              void* d_out, int out_size)
{
    const float* query = (const float*)d_in[0];
    const float* key_  = (const float*)d_in[1];
    const float* value = (const float*)d_in[2];
    const float* Wq    = (const float*)d_in[3];
    const float* bq    = (const float*)d_in[4];
    const float* Wk    = (const float*)d_in[5];
    const float* bk    = (const float*)d_in[6];
    const float* Wv    = (const float*)d_in[7];
    const float* bv    = (const float*)d_in[8];
    const float* Wo    = (const float*)d_in[9];
    const float* bo    = (const float*)d_in[10];

    float* out_main = (float*)d_out;                          // [B,S,DM]
    float* out_avg  = out_main + (size_t)ROWS * DM;           // [B,S,S]

    float *Qh, *Kh, *Vp, *Sc, *Mb, *Lb, *Ao;
    cudaGetSymbolAddress((void**)&Qh, g_Qh);
    cudaGetSymbolAddress((void**)&Kh, g_Kh);
    cudaGetSymbolAddress((void**)&Vp, g_Vp);
    cudaGetSymbolAddress((void**)&Sc, g_scores);
    cudaGetSymbolAddress((void**)&Mb, g_m);
    cudaGetSymbolAddress((void**)&Lb, g_l);
    cudaGetSymbolAddress((void**)&Ao, g_ao);

    dim3 blk(256);

    // 1) Q projection -> head layout  (M=4096, N=1024, K=1024)
    sgemm_kernel<false, true, true><<<dim3(DM / TS, ROWS / TS, 1), blk>>>(
        query, Wq, bq, Qh, ROWS, DM, DM, DM, DM, 0, 0, 0, 0, 1.0f);

    // 2) K projection -> head layout
    sgemm_kernel<false, true, true><<<dim3(DM / TS, ROWS / TS, 1), blk>>>(
        key_, Wk, bk, Kh, ROWS, DM, DM, DM, DM, 0, 0, 0, 0, 1.0f);

    // 3) V projection  (M=4096, N=64, K=1024)
    sgemm_kernel<false, false, true><<<dim3(1, ROWS / TS, 1), blk>>>(
        value, Wv, bv, Vp, ROWS, DK, DM, DM, DK, DK, 0, 0, 0, 1.0f);

    // 4) scores = Q @ K^T / 8, batched over b*h  (M=N=2048, K=64)
    sgemm_kernel<true, false, false><<<dim3(SS / TS, SS / TS, BB * HH), blk>>>(
        Qh, Kh, nullptr, Sc, SS, SS, DK, DK, DK, SS,
        (long long)SS * DK, (long long)SS * DK, (long long)SS * SS, 0.125f);

    // 5) per-row softmax stats
    rowstats_kernel<<<(BB * HH * SS) / 8, blk>>>(Sc, Mb, Lb);

    // 6) head-averaged attention matrix -> second output
    avg_kernel<<<dim3(SS, BB, 1), blk>>>(Sc, Mb, Lb, out_avg);

    // 7) attn_output = avg_attn @ V, batched over b  (M=2048, N=64, K=2048)
    sgemm_kernel<false, false, false><<<dim3(1, SS / TS, BB), blk>>>(
        out_avg, Vp, nullptr, Ao, SS, DK, SS, SS, DK, DK,
        (long long)SS * SS, (long long)SS * DK, (long long)SS * DK, 1.0f);

    // 8) output = attn_output @ Wo + bo  (M=4096, N=1024, K=64)
    sgemm_kernel<false, false, true><<<dim3(DM / TS, ROWS / TS, 1), blk>>>(
        Ao, Wo, bo, out_main, ROWS, DM, DK, DK, DM, DM, 0, 0, 0, 1.0f);
}

// round 2
// speedup vs baseline: 1.1616x; 1.1616x over previous
#include <cuda_runtime.h>

#define BB 2
#define SS 2048
#define HH 16
#define DK 64
#define DM 1024
#define ROWS (BB*SS)          // 4096

// ---------------- scratch -----------------------------------------------------
__device__ float g_Qh[(size_t)BB*HH*SS*DK];       // [b,h,s,d]
__device__ float g_Kh[(size_t)BB*HH*SS*DK];
__device__ float g_Vp[(size_t)ROWS*DK];
__device__ float g_scores[(size_t)BB*HH*SS*SS];   // 536 MB raw scaled scores (reused as av-partials later)
__device__ float g_mpart[(size_t)BB*HH*16*SS];    // per (bh, ktile, q) partial max
__device__ float g_lpart[(size_t)BB*HH*16*SS];    // per-tile partial sumexp
__device__ float g_c[(size_t)BB*HH*SS];           // c = -(m + ln l)
__device__ float g_ao[(size_t)ROWS*DK];           // attn_output

// ---------------- helpers -----------------------------------------------------
__device__ __forceinline__ float fast_exp(float x) {
    // FFMA-pipe exp (avoids MUFU bottleneck). |rel err| ~1e-7.
    x = fmaxf(x, -87.0f);
    float t = fmaf(x, 1.4426950408889634f, 12582912.0f);
    float n = t - 12582912.0f;                       // rint(x*log2e)
    float f = fmaf(x, 1.4426950408889634f, -n);      // frac in [-0.5,0.5]
    float p = 1.5403530394e-4f;
    p = fmaf(p, f, 1.3333558146e-3f);
    p = fmaf(p, f, 9.6178371906e-3f);
    p = fmaf(p, f, 5.5502813330e-2f);
    p = fmaf(p, f, 2.4022650695e-1f);
    p = fmaf(p, f, 6.9314718056e-1f);
    p = fmaf(p, f, 1.0f);
    return p * __int_as_float(((int)n + 127) << 23);
}

__device__ __forceinline__ unsigned long long pack2(float lo, float hi) {
    unsigned long long r;
    asm("mov.b64 %0, {%1, %2};" : "=l"(r) : "f"(lo), "f"(hi));
    return r;
}
__device__ __forceinline__ void unpack2(unsigned long long v, float& lo, float& hi) {
    asm("mov.b64 {%0, %1}, %2;" : "=f"(lo), "=f"(hi) : "l"(v));
}
__device__ __forceinline__ unsigned long long fma2(unsigned long long a,
                                                   unsigned long long b,
                                                   unsigned long long c) {
    unsigned long long d;
    asm("fma.rn.f32x2 %0, %1, %2, %3;" : "=l"(d) : "l"(a), "l"(b), "l"(c));
    return d;
}

// ---------------- projection GEMM: C = A[M,K]@B[K,N] + bias -------------------
// tile 128x128, 256 thr, 8x8 micro (as f32x2 pairs), KC=16, reg-staged buffer.
#define PADW 132

template<bool HEAD_OUT, bool HAS_BIAS>
__global__ __launch_bounds__(256, 2)
void proj_gemm(const float* __restrict__ A, const float* __restrict__ B,
               const float* __restrict__ bias, float* __restrict__ C,
               int N, int K, int lda, int ldb, int ldc)
{
    __shared__ __align__(16) float As[16 * PADW];
    __shared__ __align__(16) float Bs[16 * PADW];

    const int rowbase = blockIdx.y * 128;
    const int colbase = blockIdx.x * 128;
    const int tid = threadIdx.x;
    const int tx = tid & 15, ty = tid >> 4;
    const int row0 = ty * 8, col0 = tx * 8;

    float regA[8], regB[8];
    unsigned long long acc[8][4];
#pragma unroll
    for (int i = 0; i < 8; i++)
#pragma unroll
        for (int j = 0; j < 4; j++) acc[i][j] = 0ull;

    // first tile loads
#pragma unroll
    for (int i = 0; i < 8; i++) {
        int idx = tid + i * 256; int r = idx >> 4, kk = idx & 15;
        regA[i] = A[(long long)(rowbase + r) * lda + kk];
    }
#pragma unroll
    for (int i = 0; i < 8; i++) {
        int idx = tid + i * 256; int kk = idx >> 7, c = idx & 127;
        int col = colbase + c;
        regB[i] = (col < N) ? B[(long long)kk * ldb + col] : 0.f;
    }
#pragma unroll
    for (int i = 0; i < 8; i++) {
        int idx = tid + i * 256; int r = idx >> 4, kk = idx & 15;
        As[kk * PADW + r] = regA[i];
    }
#pragma unroll
    for (int i = 0; i < 8; i++) {
        int idx = tid + i * 256; int kk = idx >> 7, c = idx & 127;
        Bs[kk * PADW + c] = regB[i];
    }
    __syncthreads();

    for (int k0 = 16; ; k0 += 16) {
        const bool more = (k0 < K);
        if (more) {
#pragma unroll
            for (int i = 0; i < 8; i++) {
                int idx = tid + i * 256; int r = idx >> 4, kk = idx & 15;
                regA[i] = A[(long long)(rowbase + r) * lda + k0 + kk];
            }
#pragma unroll
            for (int i = 0; i < 8; i++) {
                int idx = tid + i * 256; int kk = idx >> 7, c = idx & 127;
                int col = colbase + c;
                regB[i] = (col < N) ? B[(long long)(k0 + kk) * ldb + col] : 0.f;
            }
        }
#pragma unroll
        for (int kk = 0; kk < 16; kk++) {
            float4 a0 = *(const float4*)&As[kk * PADW + row0];
            float4 a1 = *(const float4*)&As[kk * PADW + row0 + 4];
            float4 b0 = *(const float4*)&Bs[kk * PADW + col0];
            float4 b1 = *(const float4*)&Bs[kk * PADW + col0 + 4];
            float a[8] = {a0.x, a0.y, a0.z, a0.w, a1.x, a1.y, a1.z, a1.w};
            unsigned long long bp[4];
            bp[0] = pack2(b0.x, b0.y); bp[1] = pack2(b0.z, b0.w);
            bp[2] = pack2(b1.x, b1.y); bp[3] = pack2(b1.z, b1.w);
#pragma unroll
            for (int i = 0; i < 8; i++) {
                unsigned long long ap = pack2(a[i], a[i]);
#pragma unroll
                for (int j = 0; j < 4; j++) acc[i][j] = fma2(ap, bp[j], acc[i][j]);
            }
        }
        if (!more) break;
        __syncthreads();
#pragma unroll
        for (int i = 0; i < 8; i++) {
            int idx = tid + i * 256; int r = idx >> 4, kk = idx & 15;
            As[kk * PADW + r] = regA[i];
        }
#pragma unroll
        for (int i = 0; i < 8; i++) {
            int idx = tid + i * 256; int kk = idx >> 7, c = idx & 127;
            Bs[kk * PADW + c] = regB[i];
        }
        __syncthreads();
    }

    // epilogue
#pragma unroll
    for (int i = 0; i < 8; i++) {
        int gr = rowbase + row0 + i;
#pragma unroll
        for (int j2 = 0; j2 < 4; j2 += 2) {     // two float4 stores
            int col = colbase + col0 + j2 * 2;
            if (col < N) {
                float4 v;
                unpack2(acc[i][j2],     v.x, v.y);
                unpack2(acc[i][j2 + 1], v.z, v.w);
                if (HAS_BIAS) {
                    const float4 bb = *(const float4*)&bias[col];
                    v.x += bb.x; v.y += bb.y; v.z += bb.z; v.w += bb.w;
                }
                if (HEAD_OUT) {
                    int b = gr >> 11, s = gr & (SS - 1);
                    int h = col >> 6, d = col & (DK - 1);
                    *(float4*)&C[(((long long)(b * HH + h) * SS + s) << 6) + d] = v;
                } else {
                    *(float4*)&C[(long long)gr * ldc + col] = v;
                }
            }
        }
    }
}

// ---------------- scores + fused per-tile softmax partials --------------------
// scores[bh,q,k] = (Q·K)/8 for one 128x128 tile; per-row tile max & sumexp.
__global__ __launch_bounds__(256, 2)
void scores_kernel(const float* __restrict__ Qh, const float* __restrict__ Kh,
                   float* __restrict__ Sc,
                   float* __restrict__ mpart, float* __restrict__ lpart)
{
    __shared__ __align__(16) float Qs[32 * PADW];
    __shared__ __align__(16) float Ks[32 * PADW];

    const int bh = blockIdx.z;
    const int qbase = blockIdx.y * 128;
    const int kbase = blockIdx.x * 128;
    const float* Qp = Qh + ((long long)bh * SS + qbase) * DK;
    const float* Kp = Kh + ((long long)bh * SS + kbase) * DK;
    const int tid = threadIdx.x;
    const int tx = tid & 15, ty = tid >> 4;
    const int row0 = ty * 8, col0 = tx * 8;

    unsigned long long acc[8][4];
#pragma unroll
    for (int i = 0; i < 8; i++)
#pragma unroll
        for (int j = 0; j < 4; j++) acc[i][j] = 0ull;

#pragma unroll
    for (int half = 0; half < 2; half++) {
        const int koff = half * 32;
#pragma unroll
        for (int i = 0; i < 4; i++) {
            int idx = tid + i * 256;             // 0..1023 float4s
            int r = idx >> 3, d4 = (idx & 7) * 4;
            float4 q = *(const float4*)(Qp + (long long)r * DK + koff + d4);
            Qs[(d4 + 0) * PADW + r] = q.x; Qs[(d4 + 1) * PADW + r] = q.y;
            Qs[(d4 + 2) * PADW + r] = q.z; Qs[(d4 + 3) * PADW + r] = q.w;
            float4 k = *(const float4*)(Kp + (long long)r * DK + koff + d4);
            Ks[(d4 + 0) * PADW + r] = k.x; Ks[(d4 + 1) * PADW + r] = k.y;
            Ks[(d4 + 2) * PADW + r] = k.z; Ks[(d4 + 3) * PADW + r] = k.w;
        }
        __syncthreads();
#pragma unroll 8
        for (int kk = 0; kk < 32; kk++) {
            float4 a0 = *(const float4*)&Qs[kk * PADW + row0];
            float4 a1 = *(const float4*)&Qs[kk * PADW + row0 + 4];
            float4 b0 = *(const float4*)&Ks[kk * PADW + col0];
            float4 b1 = *(const float4*)&Ks[kk * PADW + col0 + 4];
            float a[8] = {a0.x, a0.y, a0.z, a0.w, a1.x, a1.y, a1.z, a1.w};
            unsigned long long bp[4];
            bp[0] = pack2(b0.x, b0.y); bp[1] = pack2(b0.z, b0.w);
            bp[2] = pack2(b1.x, b1.y); bp[3] = pack2(b1.z, b1.w);
#pragma unroll
            for (int i = 0; i < 8; i++) {
                unsigned long long ap = pack2(a[i], a[i]);
#pragma unroll
                for (int j = 0; j < 4; j++) acc[i][j] = fma2(ap, bp[j], acc[i][j]);
            }
        }
        __syncthreads();
    }

    // epilogue: scale, store scores, per-row tile stats (16 threads share a row)
    float* Cp = Sc + ((long long)bh * SS + qbase) * SS + kbase;
#pragma unroll
    for (int i = 0; i < 8; i++) {
        float v[8];
        unpack2(acc[i][0], v[0], v[1]); unpack2(acc[i][1], v[2], v[3]);
        unpack2(acc[i][2], v[4], v[5]); unpack2(acc[i][3], v[6], v[7]);
#pragma unroll
        for (int j = 0; j < 8; j++) v[j] *= 0.125f;

        // store raw scaled scores
        float4 s0 = {v[0], v[1], v[2], v[3]};
        float4 s1 = {v[4], v[5], v[6], v[7]};
        *(float4*)&Cp[(long long)(row0 + i) * SS + col0] = s0;
        *(float4*)&Cp[(long long)(row0 + i) * SS + col0 + 4] = s1;

        // row max across 8 local + 16 lanes (xor within half-warp keeps group)
        float m = v[0];
#pragma unroll
        for (int j = 1; j < 8; j++) m = fmaxf(m, v[j]);
#pragma unroll
        for (int off = 8; off; off >>= 1)
            m = fmaxf(m, __shfl_xor_sync(0xffffffffu, m, off));
        float l = 0.f;
#pragma unroll
        for (int j = 0; j < 8; j++) l += fast_exp(v[j] - m);
#pragma unroll
        for (int off = 8; off; off >>= 1)
            l += __shfl_xor_sync(0xffffffffu, l, off);
        if (tx == 0) {
            long long sidx = ((long long)bh * 16 + blockIdx.x) * SS + qbase + row0 + i;
            mpart[sidx] = m;
            lpart[sidx] = l;
        }
    }
}

// ---------------- combine tile partials -> c = -(m + ln l) --------------------
__global__ __launch_bounds__(256)
void combine_kernel(const float* __restrict__ mpart, const float* __restrict__ lpart,
                    float* __restrict__ cvec)
{
    int row = blockIdx.x * 256 + threadIdx.x;    // bh*2048 + q
    int bh = row >> 11, q = row & (SS - 1);
    float m = -1e30f, l = 0.f;
#pragma unroll
    for (int t = 0; t < 16; t++) {
        long long idx = ((long long)bh * 16 + t) * SS + q;
        float mt = mpart[idx], lt = lpart[idx];
        float mn = fmaxf(m, mt);
        l = l * fast_exp(m - mn) + lt * fast_exp(mt - mn);
        m = mn;
    }
    cvec[row] = -(m + __logf(l));
}

// ---------------- head-averaged attention -------------------------------------
__global__ __launch_bounds__(256)
void avg_kernel(const float* __restrict__ Sc, const float* __restrict__ cvec,
                float* __restrict__ avg)
{
    const int q = blockIdx.x;
    const int b = blockIdx.y;
    const int tid = threadIdx.x;

    __shared__ float c[HH];
    if (tid < HH) c[tid] = cvec[((long long)(b * HH + tid) << 11) + q];
    __syncthreads();

    const float* base = Sc + ((long long)(b * HH) * SS + q) * SS;
    float* dst = avg + ((long long)b * SS + q) * SS;
    for (int k0 = tid * 4; k0 < SS; k0 += 1024) {
        float ax = 0.f, ay = 0.f, az = 0.f, aw = 0.f;
#pragma unroll
        for (int h = 0; h < HH; h++) {
            const float4 s = *(const float4*)(base + (long long)h * SS * SS + k0);
            float ch = c[h];
            ax += fast_exp(s.x + ch); ay += fast_exp(s.y + ch);
            az += fast_exp(s.z + ch); aw += fast_exp(s.w + ch);
        }
        float4 o = {ax * (1.0f / HH), ay * (1.0f / HH), az * (1.0f / HH), aw * (1.0f / HH)};
        *(float4*)&dst[k0] = o;
    }
}

// ---------------- avg @ V (split-K partials) ----------------------------------
__global__ __launch_bounds__(256)
void av_gemm(const float* __restrict__ avg, const float* __restrict__ V,
             float* __restrict__ part)
{
    __shared__ float As[16 * PADW];
    __shared__ float Bs[16 * 68];
    const int b = blockIdx.z;
    const int rowbase = blockIdx.y * 128;
    const int k0base = blockIdx.x * 256;
    const float* Ap = avg + ((long long)b * SS + rowbase) * SS;
    const float* Vp = V + (long long)b * SS * DK;
    const int tid = threadIdx.x;
    const int tx = tid & 15, ty = tid >> 4;

    float acc[8][4];
#pragma unroll
    for (int i = 0; i < 8; i++)
#pragma unroll
        for (int j = 0; j < 4; j++) acc[i][j] = 0.f;

    for (int kc = 0; kc < 256; kc += 16) {
        const int k0 = k0base + kc;
#pragma unroll
        for (int i = 0; i < 8; i++) {
            int idx = tid + i * 256; int r = idx >> 4, kk = idx & 15;
            As[kk * PADW + r] = Ap[(long long)r * SS + k0 + kk];
        }
#pragma unroll
        for (int i = 0; i < 4; i++) {
            int idx = tid + i * 256; int kk = idx >> 6, cc = idx & 63;
            Bs[kk * 68 + cc] = Vp[(long long)(k0 + kk) * DK + cc];
        }
        __syncthreads();
#pragma unroll
        for (int kk = 0; kk < 16; kk++) {
            float a[8];
#pragma unroll
            for (int i = 0; i < 8; i++) a[i] = As[kk * PADW + ty * 8 + i];
            float4 bv = *(const float4*)&Bs[kk * 68 + tx * 4];
#pragma unroll
            for (int i = 0; i < 8; i++) {
                acc[i][0] = fmaf(a[i], bv.x, acc[i][0]);
                acc[i][1] = fmaf(a[i], bv.y, acc[i][1]);
                acc[i][2] = fmaf(a[i], bv.z, acc[i][2]);
                acc[i][3] = fmaf(a[i], bv.w, acc[i][3]);
            }
        }
        __syncthreads();
    }
    float* P = part + ((long long)(blockIdx.x * BB + b) * SS + rowbase) * DK;
#pragma unroll
    for (int i = 0; i < 8; i++) {
        float4 v = {acc[i][0], acc[i][1], acc[i][2], acc[i][3]};
        *(float4*)&P[(long long)(ty * 8 + i) * DK + tx * 4] = v;
    }
}

__global__ __launch_bounds__(256)
void av_reduce(const float* __restrict__ part, float* __restrict__ Ao)
{
    int i = blockIdx.x * 256 + threadIdx.x;     // over 2*2048*64
    float s = 0.f;
#pragma unroll
    for (int t = 0; t < 8; t++) s += part[(long long)t * (BB * SS * DK) + i];
    Ao[i] = s;
}

// ---------------- launch -------------------------------------------------------
extern "C" void kernel_launch(void* const* d_in, const int* in_sizes, int n_in,
                              void* d_out, int out_size)
{
    const float* query = (const float*)d_in[0];
    const float* key_  = (const float*)d_in[1];
    const float* value = (const float*)d_in[2];
    const float* Wq    = (const float*)d_in[3];
    const float* bq    = (const float*)d_in[4];
    const float* Wk    = (const float*)d_in[5];
    const float* bk    = (const float*)d_in[6];
    const float* Wv    = (const float*)d_in[7];
    const float* bv    = (const float*)d_in[8];
    const float* Wo    = (const float*)d_in[9];
    const float* bo    = (const float*)d_in[10];

    float* out_main = (float*)d_out;                 // [B,S,DM]
    float* out_avg  = out_main + (size_t)ROWS * DM;  // [B,S,S]

    float *Qh, *Kh, *Vp, *Sc, *Mp, *Lp, *Cv, *Ao;
    cudaGetSymbolAddress((void**)&Qh, g_Qh);
    cudaGetSymbolAddress((void**)&Kh, g_Kh);
    cudaGetSymbolAddress((void**)&Vp, g_Vp);
    cudaGetSymbolAddress((void**)&Sc, g_scores);
    cudaGetSymbolAddress((void**)&Mp, g_mpart);
    cudaGetSymbolAddress((void**)&Lp, g_lpart);
    cudaGetSymbolAddress((void**)&Cv, g_c);
    cudaGetSymbolAddress((void**)&Ao, g_ao);

    dim3 blk(256);

    // 1-2) Q/K projections -> head layout
    proj_gemm<true, true><<<dim3(8, 32, 1), blk>>>(query, Wq, bq, Qh, DM, DM, DM, DM, 0);
    proj_gemm<true, true><<<dim3(8, 32, 1), blk>>>(key_, Wk, bk, Kh, DM, DM, DM, DM, 0);

    // 3) V projection
    proj_gemm<false, true><<<dim3(1, 32, 1), blk>>>(value, Wv, bv, Vp, DK, DM, DM, DK, DK);

    // 4) scores + per-tile softmax partials
    scores_kernel<<<dim3(16, 16, BB * HH), blk>>>(Qh, Kh, Sc, Mp, Lp);

    // 5) combine partials -> c
    combine_kernel<<<dim3(BB * HH * SS / 256, 1, 1), blk>>>(Mp, Lp, Cv);

    // 6) head-averaged attention -> second output
    avg_kernel<<<dim3(SS, BB, 1), blk>>>(Sc, Cv, out_avg);

    // 7) attn_output = avg @ V (split-K=8, partials into g_scores scratch)
    av_gemm<<<dim3(8, 16, BB), blk>>>(out_avg, Vp, Sc);
    av_reduce<<<dim3(BB * SS * DK / 256, 1, 1), blk>>>(Sc, Ao);

    // 8) output = attn_output @ Wo + bo
    proj_gemm<false, true><<<dim3(8, 32, 1), blk>>>(Ao, Wo, bo, out_main, DM, DK, DK, DM, DM);
}

// round 4
// speedup vs baseline: 1.5818x; 1.3617x over previous
#include <cuda_runtime.h>
#include <cstdint>

#define BB 2
#define SS 2048
#define HH 16
#define DK 64
#define DM 1024
#define ROWS (BB*SS)          // 4096

// ---------------- scratch -----------------------------------------------------
__device__ float g_Qh[(size_t)BB*HH*SS*DK];       // [b,h,s,d]
__device__ float g_Kh[(size_t)BB*HH*SS*DK];
__device__ float g_Vp[(size_t)ROWS*DK];
__device__ float g_lpart[(size_t)BB*HH*16*SS];    // per (bh, ktile, q) partial sumexp
__device__ float g_c[(size_t)BB*HH*SS];           // c = -ln(l)
__device__ float g_ao[(size_t)ROWS*DK];           // attn_output
__device__ float g_avpart[(size_t)8*BB*SS*DK];    // split-K partials for avg@V

// ---------------- generic helpers ---------------------------------------------
__device__ __forceinline__ float fast_exp(float x) {
    x = fmaxf(x, -87.0f);
    float t = fmaf(x, 1.4426950408889634f, 12582912.0f);
    float n = t - 12582912.0f;
    float f = fmaf(x, 1.4426950408889634f, -n);
    float p = 1.5403530394e-4f;
    p = fmaf(p, f, 1.3333558146e-3f);
    p = fmaf(p, f, 9.6178371906e-3f);
    p = fmaf(p, f, 5.5502813330e-2f);
    p = fmaf(p, f, 2.4022650695e-1f);
    p = fmaf(p, f, 6.9314718056e-1f);
    p = fmaf(p, f, 1.0f);
    return p * __int_as_float(((int)n + 127) << 23);
}

__device__ __forceinline__ unsigned long long pack2(float lo, float hi) {
    unsigned long long r;
    asm("mov.b64 %0, {%1, %2};" : "=l"(r) : "f"(lo), "f"(hi));
    return r;
}
__device__ __forceinline__ void unpack2(unsigned long long v, float& lo, float& hi) {
    asm("mov.b64 {%0, %1}, %2;" : "=f"(lo), "=f"(hi) : "l"(v));
}
__device__ __forceinline__ unsigned long long fma2(unsigned long long a,
                                                   unsigned long long b,
                                                   unsigned long long c) {
    unsigned long long d;
    asm("fma.rn.f32x2 %0, %1, %2, %3;" : "=l"(d) : "l"(a), "l"(b), "l"(c));
    return d;
}

// ---------------- mma.sync tf32 helpers ----------------------------------------
__device__ __forceinline__ void mma8(float* c, const uint32_t* a, const uint32_t* b) {
    asm volatile("mma.sync.aligned.m16n8k8.row.col.f32.tf32.tf32.f32 "
        "{%0,%1,%2,%3}, {%4,%5,%6,%7}, {%8,%9}, {%0,%1,%2,%3};"
        : "+f"(c[0]), "+f"(c[1]), "+f"(c[2]), "+f"(c[3])
        : "r"(a[0]), "r"(a[1]), "r"(a[2]), "r"(a[3]), "r"(b[0]), "r"(b[1]));
}

__device__ __forceinline__ void split_tf32(float x, uint32_t& hi, uint32_t& lo) {
    uint32_t h;
    asm("cvt.rna.tf32.f32 %0, %1;" : "=r"(h) : "f"(x));
    float hf = __uint_as_float(h);
    asm("cvt.rna.tf32.f32 %0, %1;" : "=r"(lo) : "f"(x - hf));
    hi = h;
}

#define QK_STRIDE 68   // padded floats per row (16B-aligned rows, conflict-free)

// core: acc[2][4][4] = Q(128x64) @ K(128x64)^T warp-subtile (rows wm*32.., cols wn*32..)
__device__ __forceinline__ void score_tile(const float* __restrict__ Qs,
                                           const float* __restrict__ Ks,
                                           int wm, int wn, int gid, int tig,
                                           float acc[2][4][4])
{
#pragma unroll
    for (int mt = 0; mt < 2; mt++)
#pragma unroll
        for (int nt = 0; nt < 4; nt++)
#pragma unroll
            for (int c = 0; c < 4; c++) acc[mt][nt][c] = 0.f;

#pragma unroll
    for (int k8 = 0; k8 < 8; k8++) {
        const int k0 = k8 * 8;
        uint32_t bhf[4][2], blf[4][2];
#pragma unroll
        for (int nt = 0; nt < 4; nt++) {
            const float* kp = Ks + (wn * 32 + nt * 8 + gid) * QK_STRIDE + k0 + tig;
            split_tf32(kp[0], bhf[nt][0], blf[nt][0]);
            split_tf32(kp[4], bhf[nt][1], blf[nt][1]);
        }
#pragma unroll
        for (int mt = 0; mt < 2; mt++) {
            const float* qp = Qs + (wm * 32 + mt * 16 + gid) * QK_STRIDE + k0 + tig;
            uint32_t ah[4], al[4];
            split_tf32(qp[0],                 ah[0], al[0]);
            split_tf32(qp[8 * QK_STRIDE],     ah[1], al[1]);
            split_tf32(qp[4],                 ah[2], al[2]);
            split_tf32(qp[8 * QK_STRIDE + 4], ah[3], al[3]);
#pragma unroll
            for (int nt = 0; nt < 4; nt++) {
                mma8(acc[mt][nt], ah, bhf[nt]);   // hi*hi
                mma8(acc[mt][nt], al, bhf[nt]);   // lo*hi
                mma8(acc[mt][nt], ah, blf[nt]);   // hi*lo
            }
        }
    }
}

// ---------------- pass 1: scores tile -> per-row sumexp partials ----------------
__global__ __launch_bounds__(512, 1)
void mma_pass1(const float* __restrict__ Qh, const float* __restrict__ Kh,
               float* __restrict__ lpart)
{
    extern __shared__ float smf[];
    float* Qs = smf;                          // [128][68]
    float* Ks = smf + 128 * QK_STRIDE;        // [128][68]
    float* rowsum = Ks + 128 * QK_STRIDE;     // [128][4]

    const int tid = threadIdx.x;
    const int kt = blockIdx.x, qt = blockIdx.y, bh = blockIdx.z;
    const float* Qp = Qh + ((long long)bh * SS + qt * 128) * DK;
    const float* Kp = Kh + ((long long)bh * SS + kt * 128) * DK;

#pragma unroll
    for (int i = 0; i < 4; i++) {
        int idx = tid + i * 512;              // 0..2047 float4s
        int r = idx >> 4, c = (idx & 15) * 4;
        *(float4*)&Qs[r * QK_STRIDE + c] = *(const float4*)(Qp + r * DK + c);
        *(float4*)&Ks[r * QK_STRIDE + c] = *(const float4*)(Kp + r * DK + c);
    }
    __syncthreads();

    const int wid = tid >> 5, lane = tid & 31;
    const int wm = wid >> 2, wn = wid & 3;
    const int gid = lane >> 2, tig = lane & 3;

    float acc[2][4][4];
    score_tile(Qs, Ks, wm, wn, gid, tig, acc);

    float p[2][2];
#pragma unroll
    for (int mt = 0; mt < 2; mt++) { p[mt][0] = 0.f; p[mt][1] = 0.f; }
#pragma unroll
    for (int mt = 0; mt < 2; mt++)
#pragma unroll
        for (int nt = 0; nt < 4; nt++) {
            p[mt][0] += fast_exp(acc[mt][nt][0] * 0.125f) + fast_exp(acc[mt][nt][1] * 0.125f);
            p[mt][1] += fast_exp(acc[mt][nt][2] * 0.125f) + fast_exp(acc[mt][nt][3] * 0.125f);
        }
#pragma unroll
    for (int o = 1; o <= 2; o <<= 1)
#pragma unroll
        for (int mt = 0; mt < 2; mt++) {
            p[mt][0] += __shfl_xor_sync(0xffffffffu, p[mt][0], o);
            p[mt][1] += __shfl_xor_sync(0xffffffffu, p[mt][1], o);
        }
    if (tig == 0) {
#pragma unroll
        for (int mt = 0; mt < 2; mt++)
#pragma unroll
            for (int j = 0; j < 2; j++) {
                int r = wm * 32 + mt * 16 + j * 8 + gid;
                rowsum[r * 4 + wn] = p[mt][j];
            }
    }
    __syncthreads();
    if (tid < 128) {
        float l = rowsum[tid * 4] + rowsum[tid * 4 + 1]
                + rowsum[tid * 4 + 2] + rowsum[tid * 4 + 3];
        lpart[(long long)(bh * 16 + kt) * SS + qt * 128 + tid] = l;
    }
}

// ---------------- combine: c = -ln(sum of partials) -----------------------------
__global__ __launch_bounds__(256)
void combine_kernel(const float* __restrict__ lpart, float* __restrict__ cvec)
{
    int rowg = blockIdx.x * 256 + threadIdx.x;     // bh*2048 + q
    int bh = rowg >> 11, q = rowg & (SS - 1);
    float l = 0.f;
#pragma unroll
    for (int t = 0; t < 16; t++)
        l += lpart[(long long)(bh * 16 + t) * SS + q];
    cvec[rowg] = -__logf(l);
}

// ---------------- pass 2: recompute, exp, head-average -> out_avg ---------------
__global__ __launch_bounds__(512, 1)
void mma_pass2(const float* __restrict__ Qh, const float* __restrict__ Kh,
               const float* __restrict__ cvec, float* __restrict__ out_avg)
{
    extern __shared__ float smf[];
    float* Qs = smf;
    float* Ks = smf + 128 * QK_STRIDE;
    float* cv = Ks + 128 * QK_STRIDE;          // [16][128]

    const int tid = threadIdx.x;
    const int kt = blockIdx.x, qt = blockIdx.y, b = blockIdx.z;

#pragma unroll
    for (int i = 0; i < 4; i++) {
        int idx = tid + i * 512;               // 0..2047
        int h = idx >> 7, r = idx & 127;
        cv[idx] = cvec[(long long)(b * HH + h) * SS + qt * 128 + r];
    }

    const int wid = tid >> 5, lane = tid & 31;
    const int wm = wid >> 2, wn = wid & 3;
    const int gid = lane >> 2, tig = lane & 3;

    float eacc[2][4][4];
#pragma unroll
    for (int mt = 0; mt < 2; mt++)
#pragma unroll
        for (int nt = 0; nt < 4; nt++)
#pragma unroll
            for (int c = 0; c < 4; c++) eacc[mt][nt][c] = 0.f;

    for (int h = 0; h < HH; h++) {
        __syncthreads();    // previous iter's smem reads done / cv load visible
        const int bh = b * HH + h;
        const float* Qp = Qh + ((long long)bh * SS + qt * 128) * DK;
        const float* Kp = Kh + ((long long)bh * SS + kt * 128) * DK;
#pragma unroll
        for (int i = 0; i < 4; i++) {
            int idx = tid + i * 512;
            int r = idx >> 4, c = (idx & 15) * 4;
            *(float4*)&Qs[r * QK_STRIDE + c] = *(const float4*)(Qp + r * DK + c);
            *(float4*)&Ks[r * QK_STRIDE + c] = *(const float4*)(Kp + r * DK + c);
        }
        __syncthreads();

        float acc[2][4][4];
        score_tile(Qs, Ks, wm, wn, gid, tig, acc);

#pragma unroll
        for (int mt = 0; mt < 2; mt++) {
            float c0 = cv[h * 128 + wm * 32 + mt * 16 + gid];
            float c1 = cv[h * 128 + wm * 32 + mt * 16 + gid + 8];
#pragma unroll
            for (int nt = 0; nt < 4; nt++) {
                eacc[mt][nt][0] += fast_exp(fmaf(acc[mt][nt][0], 0.125f, c0));
                eacc[mt][nt][1] += fast_exp(fmaf(acc[mt][nt][1], 0.125f, c0));
                eacc[mt][nt][2] += fast_exp(fmaf(acc[mt][nt][2], 0.125f, c1));
                eacc[mt][nt][3] += fast_exp(fmaf(acc[mt][nt][3], 0.125f, c1));
            }
        }
    }

#pragma unroll
    for (int mt = 0; mt < 2; mt++)
#pragma unroll
        for (int nt = 0; nt < 4; nt++) {
            int r0 = qt * 128 + wm * 32 + mt * 16 + gid;
            int col = kt * 128 + wn * 32 + nt * 8 + tig * 2;
            float2 v0 = {eacc[mt][nt][0] * (1.0f / HH), eacc[mt][nt][1] * (1.0f / HH)};
            float2 v1 = {eacc[mt][nt][2] * (1.0f / HH), eacc[mt][nt][3] * (1.0f / HH)};
            *(float2*)&out_avg[((long long)b * SS + r0) * SS + col] = v0;
            *(float2*)&out_avg[((long long)b * SS + r0 + 8) * SS + col] = v1;
        }
}

// ---------------- projection GEMM (SIMT f32x2) ----------------------------------
#define PADW 132

template<bool HEAD_OUT, bool HAS_BIAS>
__global__ __launch_bounds__(256, 2)
void proj_gemm(const float* __restrict__ A, const float* __restrict__ B,
               const float* __restrict__ bias, float* __restrict__ C,
               int N, int K, int lda, int ldb, int ldc)
{
    __shared__ __align__(16) float As[16 * PADW];
    __shared__ __align__(16) float Bs[16 * PADW];

    const int rowbase = blockIdx.y * 128;
    const int colbase = blockIdx.x * 128;
    const int tid = threadIdx.x;
    const int tx = tid & 15, ty = tid >> 4;
    const int row0 = ty * 8, col0 = tx * 8;

    float regA[8], regB[8];
    unsigned long long acc[8][4];
#pragma unroll
    for (int i = 0; i < 8; i++)
#pragma unroll
        for (int j = 0; j < 4; j++) acc[i][j] = 0ull;

#pragma unroll
    for (int i = 0; i < 8; i++) {
        int idx = tid + i * 256; int r = idx >> 4, kk = idx & 15;
        regA[i] = A[(long long)(rowbase + r) * lda + kk];
    }
#pragma unroll
    for (int i = 0; i < 8; i++) {
        int idx = tid + i * 256; int kk = idx >> 7, c = idx & 127;
        int col = colbase + c;
        regB[i] = (col < N) ? B[(long long)kk * ldb + col] : 0.f;
    }
#pragma unroll
    for (int i = 0; i < 8; i++) {
        int idx = tid + i * 256; int r = idx >> 4, kk = idx & 15;
        As[kk * PADW + r] = regA[i];
    }
#pragma unroll
    for (int i = 0; i < 8; i++) {
        int idx = tid + i * 256; int kk = idx >> 7, c = idx & 127;
        Bs[kk * PADW + c] = regB[i];
    }
    __syncthreads();

    for (int k0 = 16; ; k0 += 16) {
        const bool more = (k0 < K);
        if (more) {
#pragma unroll
            for (int i = 0; i < 8; i++) {
                int idx = tid + i * 256; int r = idx >> 4, kk = idx & 15;
                regA[i] = A[(long long)(rowbase + r) * lda + k0 + kk];
            }
#pragma unroll
            for (int i = 0; i < 8; i++) {
                int idx = tid + i * 256; int kk = idx >> 7, c = idx & 127;
                int col = colbase + c;
                regB[i] = (col < N) ? B[(long long)(k0 + kk) * ldb + col] : 0.f;
            }
        }
#pragma unroll
        for (int kk = 0; kk < 16; kk++) {
            float4 a0 = *(const float4*)&As[kk * PADW + row0];
            float4 a1 = *(const float4*)&As[kk * PADW + row0 + 4];
            float4 b0 = *(const float4*)&Bs[kk * PADW + col0];
            float4 b1 = *(const float4*)&Bs[kk * PADW + col0 + 4];
            float a[8] = {a0.x, a0.y, a0.z, a0.w, a1.x, a1.y, a1.z, a1.w};
            unsigned long long bp[4];
            bp[0] = pack2(b0.x, b0.y); bp[1] = pack2(b0.z, b0.w);
            bp[2] = pack2(b1.x, b1.y); bp[3] = pack2(b1.z, b1.w);
#pragma unroll
            for (int i = 0; i < 8; i++) {
                unsigned long long ap = pack2(a[i], a[i]);
#pragma unroll
                for (int j = 0; j < 4; j++) acc[i][j] = fma2(ap, bp[j], acc[i][j]);
            }
        }
        if (!more) break;
        __syncthreads();
#pragma unroll
        for (int i = 0; i < 8; i++) {
            int idx = tid + i * 256; int r = idx >> 4, kk = idx & 15;
            As[kk * PADW + r] = regA[i];
        }
#pragma unroll
        for (int i = 0; i < 8; i++) {
            int idx = tid + i * 256; int kk = idx >> 7, c = idx & 127;
            Bs[kk * PADW + c] = regB[i];
        }
        __syncthreads();
    }

#pragma unroll
    for (int i = 0; i < 8; i++) {
        int gr = rowbase + row0 + i;
#pragma unroll
        for (int j2 = 0; j2 < 4; j2 += 2) {
            int col = colbase + col0 + j2 * 2;
            if (col < N) {
                float4 v;
                unpack2(acc[i][j2],     v.x, v.y);
                unpack2(acc[i][j2 + 1], v.z, v.w);
                if (HAS_BIAS) {
                    const float4 bb = *(const float4*)&bias[col];
                    v.x += bb.x; v.y += bb.y; v.z += bb.z; v.w += bb.w;
                }
                if (HEAD_OUT) {
                    int b = gr >> 11, s = gr & (SS - 1);
                    int h = col >> 6, d = col & (DK - 1);
                    *(float4*)&C[(((long long)(b * HH + h) * SS + s) << 6) + d] = v;
                } else {
                    *(float4*)&C[(long long)gr * ldc + col] = v;
                }
            }
        }
    }
}

// ---------------- avg @ V (split-K partials) -------------------------------------
__global__ __launch_bounds__(256)
void av_gemm(const float* __restrict__ avg, const float* __restrict__ V,
             float* __restrict__ part)
{
    __shared__ float As[16 * PADW];
    __shared__ float Bs[16 * 68];
    const int b = blockIdx.z;
    const int rowbase = blockIdx.y * 128;
    const int k0base = blockIdx.x * 256;
    const float* Ap = avg + ((long long)b * SS + rowbase) * SS;
    const float* Vp = V + (long long)b * SS * DK;
    const int tid = threadIdx.x;
    const int tx = tid & 15, ty = tid >> 4;

    float acc[8][4];
#pragma unroll
    for (int i = 0; i < 8; i++)
#pragma unroll
        for (int j = 0; j < 4; j++) acc[i][j] = 0.f;

    for (int kc = 0; kc < 256; kc += 16) {
        const int k0 = k0base + kc;
#pragma unroll
        for (int i = 0; i < 8; i++) {
            int idx = tid + i * 256; int r = idx >> 4, kk = idx & 15;
            As[kk * PADW + r] = Ap[(long long)r * SS + k0 + kk];
        }
#pragma unroll
        for (int i = 0; i < 4; i++) {
            int idx = tid + i * 256; int kk = idx >> 6, cc = idx & 63;
            Bs[kk * 68 + cc] = Vp[(long long)(k0 + kk) * DK + cc];
        }
        __syncthreads();
#pragma unroll
        for (int kk = 0; kk < 16; kk++) {
            float a[8];
#pragma unroll
            for (int i = 0; i < 8; i++) a[i] = As[kk * PADW + ty * 8 + i];
            float4 bv = *(const float4*)&Bs[kk * 68 + tx * 4];
#pragma unroll
            for (int i = 0; i < 8; i++) {
                acc[i][0] = fmaf(a[i], bv.x, acc[i][0]);
                acc[i][1] = fmaf(a[i], bv.y, acc[i][1]);
                acc[i][2] = fmaf(a[i], bv.z, acc[i][2]);
                acc[i][3] = fmaf(a[i], bv.w, acc[i][3]);
            }
        }
        __syncthreads();
    }
    float* P = part + ((long long)(blockIdx.x * BB + b) * SS + rowbase) * DK;
#pragma unroll
    for (int i = 0; i < 8; i++) {
        float4 v = {acc[i][0], acc[i][1], acc[i][2], acc[i][3]};
        *(float4*)&P[(long long)(ty * 8 + i) * DK + tx * 4] = v;
    }
}

__global__ __launch_bounds__(256)
void av_reduce(const float* __restrict__ part, float* __restrict__ Ao)
{
    int i = blockIdx.x * 256 + threadIdx.x;
    float s = 0.f;
#pragma unroll
    for (int t = 0; t < 8; t++) s += part[(long long)t * (BB * SS * DK) + i];
    Ao[i] = s;
}

// ---------------- launch -----------------------------------------------------------
extern "C" void kernel_launch(void* const* d_in, const int* in_sizes, int n_in,
                              void* d_out, int out_size)
{
    const float* query = (const float*)d_in[0];
    const float* key_  = (const float*)d_in[1];
    const float* value = (const float*)d_in[2];
    const float* Wq    = (const float*)d_in[3];
    const float* bq    = (const float*)d_in[4];
    const float* Wk    = (const float*)d_in[5];
    const float* bk    = (const float*)d_in[6];
    const float* Wv    = (const float*)d_in[7];
    const float* bv    = (const float*)d_in[8];
    const float* Wo    = (const float*)d_in[9];
    const float* bo    = (const float*)d_in[10];

    float* out_main = (float*)d_out;                 // [B,S,DM]
    float* out_avg  = out_main + (size_t)ROWS * DM;  // [B,S,S]

    float *Qh, *Kh, *Vp, *Lp, *Cv, *Ao, *Av;
    cudaGetSymbolAddress((void**)&Qh, g_Qh);
    cudaGetSymbolAddress((void**)&Kh, g_Kh);
    cudaGetSymbolAddress((void**)&Vp, g_Vp);
    cudaGetSymbolAddress((void**)&Lp, g_lpart);
    cudaGetSymbolAddress((void**)&Cv, g_c);
    cudaGetSymbolAddress((void**)&Ao, g_ao);
    cudaGetSymbolAddress((void**)&Av, g_avpart);

    const int smem1 = (2 * 128 * QK_STRIDE + 128 * 4) * 4;       // tiles + rowsum
    const int smem2 = (2 * 128 * QK_STRIDE + 16 * 128) * 4;      // tiles + cv
    cudaFuncSetAttribute(mma_pass1, cudaFuncAttributeMaxDynamicSharedMemorySize, smem1);
    cudaFuncSetAttribute(mma_pass2, cudaFuncAttributeMaxDynamicSharedMemorySize, smem2);

    dim3 blk(256);

    // 1-2) Q/K projections -> head layout
    proj_gemm<true, true><<<dim3(8, 32, 1), blk>>>(query, Wq, bq, Qh, DM, DM, DM, DM, 0);
    proj_gemm<true, true><<<dim3(8, 32, 1), blk>>>(key_, Wk, bk, Kh, DM, DM, DM, DM, 0);

    // 3) V projection
    proj_gemm<false, true><<<dim3(1, 32, 1), blk>>>(value, Wv, bv, Vp, DK, DM, DM, DK, DK);

    // 4) pass1: tf32 mma.sync scores -> per-tile sumexp partials
    mma_pass1<<<dim3(16, 16, BB * HH), 512, smem1>>>(Qh, Kh, Lp);

    // 5) combine partials -> c = -ln l
    combine_kernel<<<dim3(BB * HH * SS / 256, 1, 1), blk>>>(Lp, Cv);

    // 6) pass2: recompute scores, exp, average over heads -> out_avg
    mma_pass2<<<dim3(16, 16, BB), 512, smem2>>>(Qh, Kh, Cv, out_avg);

    // 7) attn_output = avg @ V (split-K=8)
    av_gemm<<<dim3(8, 16, BB), blk>>>(out_avg, Vp, Av);
    av_reduce<<<dim3(BB * SS * DK / 256, 1, 1), blk>>>(Av, Ao);

    // 8) output = attn_output @ Wo + bo
    proj_gemm<false, true><<<dim3(8, 32, 1), blk>>>(Ao, Wo, bo, out_main, DM, DK, DK, DM, DM);
}

// round 5
// speedup vs baseline: 1.9672x; 1.2436x over previous
#include <cuda_runtime.h>
#include <cstdint>

#define BB 2
#define SS 2048
#define HH 16
#define DK 64
#define DM 1024
#define ROWS (BB*SS)          // 4096

// ---------------- scratch -----------------------------------------------------
__device__ float g_Qhi[(size_t)BB*HH*SS*DK];      // tf32 hi, head layout [b,h,s,d]
__device__ float g_Qlo[(size_t)BB*HH*SS*DK];
__device__ float g_Khi[(size_t)BB*HH*SS*DK];
__device__ float g_Klo[(size_t)BB*HH*SS*DK];
__device__ float g_Vp[(size_t)ROWS*DK];
__device__ float g_scores[(size_t)BB*HH*SS*SS];   // fp32 scaled scores (536 MB)
__device__ float g_lpart[(size_t)BB*HH*16*SS];    // per (bh, ktile, q) partial sumexp
__device__ float g_c[(size_t)BB*HH*SS];           // c = -ln(l)
__device__ float g_ao[(size_t)ROWS*DK];           // attn_output
__device__ float g_avpart[(size_t)8*BB*SS*DK];    // split-K partials for avg@V

// ---------------- generic helpers ---------------------------------------------
__device__ __forceinline__ float fast_exp(float x) {
    x = fmaxf(x, -87.0f);
    float t = fmaf(x, 1.4426950408889634f, 12582912.0f);
    float n = t - 12582912.0f;
    float f = fmaf(x, 1.4426950408889634f, -n);
    float p = 1.5403530394e-4f;
    p = fmaf(p, f, 1.3333558146e-3f);
    p = fmaf(p, f, 9.6178371906e-3f);
    p = fmaf(p, f, 5.5502813330e-2f);
    p = fmaf(p, f, 2.4022650695e-1f);
    p = fmaf(p, f, 6.9314718056e-1f);
    p = fmaf(p, f, 1.0f);
    return p * __int_as_float(((int)n + 127) << 23);
}

__device__ __forceinline__ unsigned long long pack2(float lo, float hi) {
    unsigned long long r;
    asm("mov.b64 %0, {%1, %2};" : "=l"(r) : "f"(lo), "f"(hi));
    return r;
}
__device__ __forceinline__ void unpack2(unsigned long long v, float& lo, float& hi) {
    asm("mov.b64 {%0, %1}, %2;" : "=f"(lo), "=f"(hi) : "l"(v));
}
__device__ __forceinline__ unsigned long long fma2(unsigned long long a,
                                                   unsigned long long b,
                                                   unsigned long long c) {
    unsigned long long d;
    asm("fma.rn.f32x2 %0, %1, %2, %3;" : "=l"(d) : "l"(a), "l"(b), "l"(c));
    return d;
}

__device__ __forceinline__ void mma8(float* c, const uint32_t* a, const uint32_t* b) {
    asm volatile("mma.sync.aligned.m16n8k8.row.col.f32.tf32.tf32.f32 "
        "{%0,%1,%2,%3}, {%4,%5,%6,%7}, {%8,%9}, {%0,%1,%2,%3};"
        : "+f"(c[0]), "+f"(c[1]), "+f"(c[2]), "+f"(c[3])
        : "r"(a[0]), "r"(a[1]), "r"(a[2]), "r"(a[3]), "r"(b[0]), "r"(b[1]));
}

__device__ __forceinline__ void split_tf32(float x, float& hi, float& lo) {
    uint32_t h, l;
    asm("cvt.rna.tf32.f32 %0, %1;" : "=r"(h) : "f"(x));
    float hf = __uint_as_float(h);
    asm("cvt.rna.tf32.f32 %0, %1;" : "=r"(l) : "f"(x - hf));
    hi = hf; lo = __uint_as_float(l);
}

#define QK_STRIDE 68

// ---------------- pass 1: MMA scores -> store fp32 + per-row sumexp --------------
__global__ __launch_bounds__(512, 1)
void mma_pass1(const float* __restrict__ Qhi, const float* __restrict__ Qlo,
               const float* __restrict__ Khi, const float* __restrict__ Klo,
               float* __restrict__ Sc, float* __restrict__ lpart)
{
    extern __shared__ float smf[];
    float* Qh = smf;
    float* Ql = Qh + 128 * QK_STRIDE;
    float* Kh = Ql + 128 * QK_STRIDE;
    float* Kl = Kh + 128 * QK_STRIDE;
    float* rowsum = Kl + 128 * QK_STRIDE;     // [128][4]

    const int tid = threadIdx.x;
    const int kt = blockIdx.x, qt = blockIdx.y, bh = blockIdx.z;
    const long long qoff = ((long long)bh * SS + qt * 128) * DK;
    const long long koff = ((long long)bh * SS + kt * 128) * DK;

#pragma unroll
    for (int i = 0; i < 4; i++) {
        int idx = tid + i * 512;              // 0..2047 float4s
        int r = idx >> 4, c = (idx & 15) * 4;
        int so = r * QK_STRIDE + c;
        long long go = (long long)r * DK + c;
        *(float4*)&Qh[so] = *(const float4*)(Qhi + qoff + go);
        *(float4*)&Ql[so] = *(const float4*)(Qlo + qoff + go);
        *(float4*)&Kh[so] = *(const float4*)(Khi + koff + go);
        *(float4*)&Kl[so] = *(const float4*)(Klo + koff + go);
    }
    __syncthreads();

    const int wid = tid >> 5, lane = tid & 31;
    const int wm = wid >> 2, wn = wid & 3;
    const int gid = lane >> 2, tig = lane & 3;

    float acc[2][4][4];
#pragma unroll
    for (int mt = 0; mt < 2; mt++)
#pragma unroll
        for (int nt = 0; nt < 4; nt++)
#pragma unroll
            for (int c = 0; c < 4; c++) acc[mt][nt][c] = 0.f;

#pragma unroll
    for (int k8 = 0; k8 < 8; k8++) {
        const int k0 = k8 * 8;
        uint32_t bhf[4][2], blf[4][2];
#pragma unroll
        for (int nt = 0; nt < 4; nt++) {
            int off = (wn * 32 + nt * 8 + gid) * QK_STRIDE + k0 + tig;
            bhf[nt][0] = __float_as_uint(Kh[off]);
            bhf[nt][1] = __float_as_uint(Kh[off + 4]);
            blf[nt][0] = __float_as_uint(Kl[off]);
            blf[nt][1] = __float_as_uint(Kl[off + 4]);
        }
#pragma unroll
        for (int mt = 0; mt < 2; mt++) {
            int off = (wm * 32 + mt * 16 + gid) * QK_STRIDE + k0 + tig;
            uint32_t ah[4], al[4];
            ah[0] = __float_as_uint(Qh[off]);
            ah[1] = __float_as_uint(Qh[off + 8 * QK_STRIDE]);
            ah[2] = __float_as_uint(Qh[off + 4]);
            ah[3] = __float_as_uint(Qh[off + 8 * QK_STRIDE + 4]);
            al[0] = __float_as_uint(Ql[off]);
            al[1] = __float_as_uint(Ql[off + 8 * QK_STRIDE]);
            al[2] = __float_as_uint(Ql[off + 4]);
            al[3] = __float_as_uint(Ql[off + 8 * QK_STRIDE + 4]);
#pragma unroll
            for (int nt = 0; nt < 4; nt++) {
                mma8(acc[mt][nt], ah, bhf[nt]);   // hi*hi
                mma8(acc[mt][nt], al, bhf[nt]);   // lo*hi
                mma8(acc[mt][nt], ah, blf[nt]);   // hi*lo
            }
        }
    }

    // scale + store scores + per-row partial sumexp
    float* Cp = Sc + ((long long)bh * SS + qt * 128) * SS + kt * 128;
    float p[2][2];
    p[0][0] = p[0][1] = p[1][0] = p[1][1] = 0.f;
#pragma unroll
    for (int mt = 0; mt < 2; mt++)
#pragma unroll
        for (int nt = 0; nt < 4; nt++) {
            float s0 = acc[mt][nt][0] * 0.125f, s1 = acc[mt][nt][1] * 0.125f;
            float s2 = acc[mt][nt][2] * 0.125f, s3 = acc[mt][nt][3] * 0.125f;
            int r0 = wm * 32 + mt * 16 + gid;
            int col = wn * 32 + nt * 8 + tig * 2;
            float2 v0 = {s0, s1}, v1 = {s2, s3};
            *(float2*)&Cp[(long long)r0 * SS + col] = v0;
            *(float2*)&Cp[(long long)(r0 + 8) * SS + col] = v1;
            p[mt][0] += fast_exp(s0) + fast_exp(s1);
            p[mt][1] += fast_exp(s2) + fast_exp(s3);
        }
#pragma unroll
    for (int o = 1; o <= 2; o <<= 1)
#pragma unroll
        for (int mt = 0; mt < 2; mt++) {
            p[mt][0] += __shfl_xor_sync(0xffffffffu, p[mt][0], o);
            p[mt][1] += __shfl_xor_sync(0xffffffffu, p[mt][1], o);
        }
    if (tig == 0) {
#pragma unroll
        for (int mt = 0; mt < 2; mt++)
#pragma unroll
            for (int j = 0; j < 2; j++) {
                int r = wm * 32 + mt * 16 + j * 8 + gid;
                rowsum[r * 4 + wn] = p[mt][j];
            }
    }
    __syncthreads();
    if (tid < 128) {
        float l = rowsum[tid * 4] + rowsum[tid * 4 + 1]
                + rowsum[tid * 4 + 2] + rowsum[tid * 4 + 3];
        lpart[(long long)(bh * 16 + kt) * SS + qt * 128 + tid] = l;
    }
}

// ---------------- combine: c = -ln(sum of partials) -----------------------------
__global__ __launch_bounds__(256)
void combine_kernel(const float* __restrict__ lpart, float* __restrict__ cvec)
{
    int rowg = blockIdx.x * 256 + threadIdx.x;     // bh*2048 + q
    int bh = rowg >> 11, q = rowg & (SS - 1);
    float l = 0.f;
#pragma unroll
    for (int t = 0; t < 16; t++)
        l += lpart[(long long)(bh * 16 + t) * SS + q];
    cvec[rowg] = -__logf(l);
}

// ---------------- head-averaged attention (streaming) ----------------------------
__global__ __launch_bounds__(256)
void avg_kernel(const float* __restrict__ Sc, const float* __restrict__ cvec,
                float* __restrict__ avg)
{
    const int q = blockIdx.x;
    const int b = blockIdx.y;
    const int tid = threadIdx.x;

    __shared__ float c[HH];
    if (tid < HH) c[tid] = cvec[((long long)(b * HH + tid) << 11) + q];
    __syncthreads();

    const float* base = Sc + ((long long)(b * HH) * SS + q) * SS;
    float* dst = avg + ((long long)b * SS + q) * SS;
    for (int k0 = tid * 4; k0 < SS; k0 += 1024) {
        float ax = 0.f, ay = 0.f, az = 0.f, aw = 0.f;
#pragma unroll
        for (int h = 0; h < HH; h++) {
            const float4 s = *(const float4*)(base + (long long)h * SS * SS + k0);
            float ch = c[h];
            ax += fast_exp(s.x + ch); ay += fast_exp(s.y + ch);
            az += fast_exp(s.z + ch); aw += fast_exp(s.w + ch);
        }
        float4 o = {ax * (1.0f / HH), ay * (1.0f / HH), az * (1.0f / HH), aw * (1.0f / HH)};
        *(float4*)&dst[k0] = o;
    }
}

// ---------------- projection GEMM (SIMT f32x2) ----------------------------------
#define PADW 132

// MODE: 0 = plain [M,N] output + bias; 1 = head-layout split hi/lo outputs + bias
template<int MODE>
__global__ __launch_bounds__(256, 2)
void proj_gemm(const float* __restrict__ A, const float* __restrict__ B,
               const float* __restrict__ bias, float* __restrict__ C,
               float* __restrict__ Clo,
               int N, int K, int lda, int ldb, int ldc)
{
    __shared__ __align__(16) float As[16 * PADW];
    __shared__ __align__(16) float Bs[16 * PADW];

    const int rowbase = blockIdx.y * 128;
    const int colbase = blockIdx.x * 128;
    const int tid = threadIdx.x;
    const int tx = tid & 15, ty = tid >> 4;
    const int row0 = ty * 8, col0 = tx * 8;

    float regA[8], regB[8];
    unsigned long long acc[8][4];
#pragma unroll
    for (int i = 0; i < 8; i++)
#pragma unroll
        for (int j = 0; j < 4; j++) acc[i][j] = 0ull;

#pragma unroll
    for (int i = 0; i < 8; i++) {
        int idx = tid + i * 256; int r = idx >> 4, kk = idx & 15;
        regA[i] = A[(long long)(rowbase + r) * lda + kk];
    }
#pragma unroll
    for (int i = 0; i < 8; i++) {
        int idx = tid + i * 256; int kk = idx >> 7, c = idx & 127;
        int col = colbase + c;
        regB[i] = (col < N) ? B[(long long)kk * ldb + col] : 0.f;
    }
#pragma unroll
    for (int i = 0; i < 8; i++) {
        int idx = tid + i * 256; int r = idx >> 4, kk = idx & 15;
        As[kk * PADW + r] = regA[i];
    }
#pragma unroll
    for (int i = 0; i < 8; i++) {
        int idx = tid + i * 256; int kk = idx >> 7, c = idx & 127;
        Bs[kk * PADW + c] = regB[i];
    }
    __syncthreads();

    for (int k0 = 16; ; k0 += 16) {
        const bool more = (k0 < K);
        if (more) {
#pragma unroll
            for (int i = 0; i < 8; i++) {
                int idx = tid + i * 256; int r = idx >> 4, kk = idx & 15;
                regA[i] = A[(long long)(rowbase + r) * lda + k0 + kk];
            }
#pragma unroll
            for (int i = 0; i < 8; i++) {
                int idx = tid + i * 256; int kk = idx >> 7, c = idx & 127;
                int col = colbase + c;
                regB[i] = (col < N) ? B[(long long)(k0 + kk) * ldb + col] : 0.f;
            }
        }
#pragma unroll
        for (int kk = 0; kk < 16; kk++) {
            float4 a0 = *(const float4*)&As[kk * PADW + row0];
            float4 a1 = *(const float4*)&As[kk * PADW + row0 + 4];
            float4 b0 = *(const float4*)&Bs[kk * PADW + col0];
            float4 b1 = *(const float4*)&Bs[kk * PADW + col0 + 4];
            float a[8] = {a0.x, a0.y, a0.z, a0.w, a1.x, a1.y, a1.z, a1.w};
            unsigned long long bp[4];
            bp[0] = pack2(b0.x, b0.y); bp[1] = pack2(b0.z, b0.w);
            bp[2] = pack2(b1.x, b1.y); bp[3] = pack2(b1.z, b1.w);
#pragma unroll
            for (int i = 0; i < 8; i++) {
                unsigned long long ap = pack2(a[i], a[i]);
#pragma unroll
                for (int j = 0; j < 4; j++) acc[i][j] = fma2(ap, bp[j], acc[i][j]);
            }
        }
        if (!more) break;
        __syncthreads();
#pragma unroll
        for (int i = 0; i < 8; i++) {
            int idx = tid + i * 256; int r = idx >> 4, kk = idx & 15;
            As[kk * PADW + r] = regA[i];
        }
#pragma unroll
        for (int i = 0; i < 8; i++) {
            int idx = tid + i * 256; int kk = idx >> 7, c = idx & 127;
            Bs[kk * PADW + c] = regB[i];
        }
        __syncthreads();
    }

#pragma unroll
    for (int i = 0; i < 8; i++) {
        int gr = rowbase + row0 + i;
#pragma unroll
        for (int j2 = 0; j2 < 4; j2 += 2) {
            int col = colbase + col0 + j2 * 2;
            if (col < N) {
                float4 v;
                unpack2(acc[i][j2],     v.x, v.y);
                unpack2(acc[i][j2 + 1], v.z, v.w);
                const float4 bb = *(const float4*)&bias[col];
                v.x += bb.x; v.y += bb.y; v.z += bb.z; v.w += bb.w;
                if (MODE == 1) {
                    int b = gr >> 11, s = gr & (SS - 1);
                    int h = col >> 6, d = col & (DK - 1);
                    long long o = (((long long)(b * HH + h) * SS + s) << 6) + d;
                    float4 hv, lv;
                    split_tf32(v.x, hv.x, lv.x); split_tf32(v.y, hv.y, lv.y);
                    split_tf32(v.z, hv.z, lv.z); split_tf32(v.w, hv.w, lv.w);
                    *(float4*)&C[o] = hv;
                    *(float4*)&Clo[o] = lv;
                } else {
                    *(float4*)&C[(long long)gr * ldc + col] = v;
                }
            }
        }
    }
}

// ---------------- avg @ V (split-K partials) -------------------------------------
__global__ __launch_bounds__(256)
void av_gemm(const float* __restrict__ avg, const float* __restrict__ V,
             float* __restrict__ part)
{
    __shared__ float As[16 * PADW];
    __shared__ float Bs[16 * 68];
    const int b = blockIdx.z;
    const int rowbase = blockIdx.y * 128;
    const int k0base = blockIdx.x * 256;
    const float* Ap = avg + ((long long)b * SS + rowbase) * SS;
    const float* Vp = V + (long long)b * SS * DK;
    const int tid = threadIdx.x;
    const int tx = tid & 15, ty = tid >> 4;

    float acc[8][4];
#pragma unroll
    for (int i = 0; i < 8; i++)
#pragma unroll
        for (int j = 0; j < 4; j++) acc[i][j] = 0.f;

    for (int kc = 0; kc < 256; kc += 16) {
        const int k0 = k0base + kc;
#pragma unroll
        for (int i = 0; i < 8; i++) {
            int idx = tid + i * 256; int r = idx >> 4, kk = idx & 15;
            As[kk * PADW + r] = Ap[(long long)r * SS + k0 + kk];
        }
#pragma unroll
        for (int i = 0; i < 4; i++) {
            int idx = tid + i * 256; int kk = idx >> 6, cc = idx & 63;
            Bs[kk * 68 + cc] = Vp[(long long)(k0 + kk) * DK + cc];
        }
        __syncthreads();
#pragma unroll
        for (int kk = 0; kk < 16; kk++) {
            float a[8];
#pragma unroll
            for (int i = 0; i < 8; i++) a[i] = As[kk * PADW + ty * 8 + i];
            float4 bv = *(const float4*)&Bs[kk * 68 + tx * 4];
#pragma unroll
            for (int i = 0; i < 8; i++) {
                acc[i][0] = fmaf(a[i], bv.x, acc[i][0]);
                acc[i][1] = fmaf(a[i], bv.y, acc[i][1]);
                acc[i][2] = fmaf(a[i], bv.z, acc[i][2]);
                acc[i][3] = fmaf(a[i], bv.w, acc[i][3]);
            }
        }
        __syncthreads();
    }
    float* P = part + ((long long)(blockIdx.x * BB + b) * SS + rowbase) * DK;
#pragma unroll
    for (int i = 0; i < 8; i++) {
        float4 v = {acc[i][0], acc[i][1], acc[i][2], acc[i][3]};
        *(float4*)&P[(long long)(ty * 8 + i) * DK + tx * 4] = v;
    }
}

__global__ __launch_bounds__(256)
void av_reduce(const float* __restrict__ part, float* __restrict__ Ao)
{
    int i = blockIdx.x * 256 + threadIdx.x;
    float s = 0.f;
#pragma unroll
    for (int t = 0; t < 8; t++) s += part[(long long)t * (BB * SS * DK) + i];
    Ao[i] = s;
}

// ---------------- launch -----------------------------------------------------------
extern "C" void kernel_launch(void* const* d_in, const int* in_sizes, int n_in,
                              void* d_out, int out_size)
{
    const float* query = (const float*)d_in[0];
    const float* key_  = (const float*)d_in[1];
    const float* value = (const float*)d_in[2];
    const float* Wq    = (const float*)d_in[3];
    const float* bq    = (const float*)d_in[4];
    const float* Wk    = (const float*)d_in[5];
    const float* bk    = (const float*)d_in[6];
    const float* Wv    = (const float*)d_in[7];
    const float* bv    = (const float*)d_in[8];
    const float* Wo    = (const float*)d_in[9];
    const float* bo    = (const float*)d_in[10];

    float* out_main = (float*)d_out;                 // [B,S,DM]
    float* out_avg  = out_main + (size_t)ROWS * DM;  // [B,S,S]

    float *Qhi, *Qlo, *Khi, *Klo, *Vp, *Sc, *Lp, *Cv, *Ao, *Av;
    cudaGetSymbolAddress((void**)&Qhi, g_Qhi);
    cudaGetSymbolAddress((void**)&Qlo, g_Qlo);
    cudaGetSymbolAddress((void**)&Khi, g_Khi);
    cudaGetSymbolAddress((void**)&Klo, g_Klo);
    cudaGetSymbolAddress((void**)&Vp, g_Vp);
    cudaGetSymbolAddress((void**)&Sc, g_scores);
    cudaGetSymbolAddress((void**)&Lp, g_lpart);
    cudaGetSymbolAddress((void**)&Cv, g_c);
    cudaGetSymbolAddress((void**)&Ao, g_ao);
    cudaGetSymbolAddress((void**)&Av, g_avpart);

    const int smem1 = (4 * 128 * QK_STRIDE + 128 * 4) * 4;   // 4 tiles + rowsum
    cudaFuncSetAttribute(mma_pass1, cudaFuncAttributeMaxDynamicSharedMemorySize, smem1);

    dim3 blk(256);

    // 1-2) Q/K projections -> head-layout tf32 hi/lo
    proj_gemm<1><<<dim3(8, 32, 1), blk>>>(query, Wq, bq, Qhi, Qlo, DM, DM, DM, DM, 0);
    proj_gemm<1><<<dim3(8, 32, 1), blk>>>(key_, Wk, bk, Khi, Klo, DM, DM, DM, DM, 0);

    // 3) V projection
    proj_gemm<0><<<dim3(1, 32, 1), blk>>>(value, Wv, bv, Vp, nullptr, DK, DM, DM, DK, DK);

    // 4) pass1: tf32 mma.sync scores -> fp32 scores + sumexp partials
    mma_pass1<<<dim3(16, 16, BB * HH), 512, smem1>>>(Qhi, Qlo, Khi, Klo, Sc, Lp);

    // 5) combine partials -> c = -ln l
    combine_kernel<<<dim3(BB * HH * SS / 256, 1, 1), blk>>>(Lp, Cv);

    // 6) head-averaged attention (streaming) -> second output
    avg_kernel<<<dim3(SS, BB, 1), blk>>>(Sc, Cv, out_avg);

    // 7) attn_output = avg @ V (split-K=8)
    av_gemm<<<dim3(8, 16, BB), blk>>>(out_avg, Vp, Av);
    av_reduce<<<dim3(BB * SS * DK / 256, 1, 1), blk>>>(Av, Ao);

    // 8) output = attn_output @ Wo + bo
    proj_gemm<0><<<dim3(8, 32, 1), blk>>>(Ao, Wo, bo, out_main, nullptr, DM, DK, DK, DM, DM);
}